// round 2
// baseline (speedup 1.0000x reference)
#include <cuda_runtime.h>
#include <cuda_bf16.h>
#include <cstdint>

// Problem: B=8, S=2048, N=4, D=1024
//   mixed[b,s,i,d] = sum_j h_res[b,s,i,j] * x[b,s,j,d]
//   out = mixed * h_out[b,s,d] + h_post[b,s,i] * x[b,s,i,d]
//
// One CTA per token (b*s). 256 threads; thread t owns float4 chunk t of D
// (D/4 = 256 chunks) across all 4 streams.

#define TOKENS (8 * 2048)
#define D_DIM 1024
#define D4 (D_DIM / 4)   // 256

__global__ __launch_bounds__(256, 8)
void stream_mix_kernel(const float* __restrict__ x,
                       const float* __restrict__ h_res,
                       const float* __restrict__ h_out,
                       const float* __restrict__ h_post,
                       float* __restrict__ out) {
    const int tok = blockIdx.x;          // 0 .. TOKENS-1
    const int d4  = threadIdx.x;         // 0 .. 255

    __shared__ float4 s_hr[4];           // h_res rows (4x4)
    __shared__ float4 s_hp;              // h_post (4)

    if (threadIdx.x < 4) {
        s_hr[threadIdx.x] =
            reinterpret_cast<const float4*>(h_res + (size_t)tok * 16)[threadIdx.x];
    } else if (threadIdx.x == 4) {
        s_hp = reinterpret_cast<const float4*>(h_post + (size_t)tok * 4)[0];
    }

    // Issue the big global loads BEFORE the barrier so they overlap the sync.
    const float4* xb =
        reinterpret_cast<const float4*>(x + (size_t)tok * 4 * D_DIM);
    const float4 x0 = xb[0 * D4 + d4];
    const float4 x1 = xb[1 * D4 + d4];
    const float4 x2 = xb[2 * D4 + d4];
    const float4 x3 = xb[3 * D4 + d4];
    const float4 ho =
        reinterpret_cast<const float4*>(h_out + (size_t)tok * D_DIM)[d4];

    __syncthreads();

    const float4 hp = s_hp;
    float4* ob = reinterpret_cast<float4*>(out + (size_t)tok * 4 * D_DIM);

    // Stream 0
    {
        const float4 hr = s_hr[0];
        float4 m;
        m.x = hr.x * x0.x + hr.y * x1.x + hr.z * x2.x + hr.w * x3.x;
        m.y = hr.x * x0.y + hr.y * x1.y + hr.z * x2.y + hr.w * x3.y;
        m.z = hr.x * x0.z + hr.y * x1.z + hr.z * x2.z + hr.w * x3.z;
        m.w = hr.x * x0.w + hr.y * x1.w + hr.z * x2.w + hr.w * x3.w;
        float4 o;
        o.x = m.x * ho.x + hp.x * x0.x;
        o.y = m.y * ho.y + hp.x * x0.y;
        o.z = m.z * ho.z + hp.x * x0.z;
        o.w = m.w * ho.w + hp.x * x0.w;
        ob[0 * D4 + d4] = o;
    }
    // Stream 1
    {
        const float4 hr = s_hr[1];
        float4 m;
        m.x = hr.x * x0.x + hr.y * x1.x + hr.z * x2.x + hr.w * x3.x;
        m.y = hr.x * x0.y + hr.y * x1.y + hr.z * x2.y + hr.w * x3.y;
        m.z = hr.x * x0.z + hr.y * x1.z + hr.z * x2.z + hr.w * x3.z;
        m.w = hr.x * x0.w + hr.y * x1.w + hr.z * x2.w + hr.w * x3.w;
        float4 o;
        o.x = m.x * ho.x + hp.y * x1.x;
        o.y = m.y * ho.y + hp.y * x1.y;
        o.z = m.z * ho.z + hp.y * x1.z;
        o.w = m.w * ho.w + hp.y * x1.w;
        ob[1 * D4 + d4] = o;
    }
    // Stream 2
    {
        const float4 hr = s_hr[2];
        float4 m;
        m.x = hr.x * x0.x + hr.y * x1.x + hr.z * x2.x + hr.w * x3.x;
        m.y = hr.x * x0.y + hr.y * x1.y + hr.z * x2.y + hr.w * x3.y;
        m.z = hr.x * x0.z + hr.y * x1.z + hr.z * x2.z + hr.w * x3.z;
        m.w = hr.x * x0.w + hr.y * x1.w + hr.z * x2.w + hr.w * x3.w;
        float4 o;
        o.x = m.x * ho.x + hp.z * x2.x;
        o.y = m.y * ho.y + hp.z * x2.y;
        o.z = m.z * ho.z + hp.z * x2.z;
        o.w = m.w * ho.w + hp.z * x2.w;
        ob[2 * D4 + d4] = o;
    }
    // Stream 3
    {
        const float4 hr = s_hr[3];
        float4 m;
        m.x = hr.x * x0.x + hr.y * x1.x + hr.z * x2.x + hr.w * x3.x;
        m.y = hr.x * x0.y + hr.y * x1.y + hr.z * x2.y + hr.w * x3.y;
        m.z = hr.x * x0.z + hr.y * x1.z + hr.z * x2.z + hr.w * x3.z;
        m.w = hr.x * x0.w + hr.y * x1.w + hr.z * x2.w + hr.w * x3.w;
        float4 o;
        o.x = m.x * ho.x + hp.w * x3.x;
        o.y = m.y * ho.y + hp.w * x3.y;
        o.z = m.z * ho.z + hp.w * x3.z;
        o.w = m.w * ho.w + hp.w * x3.w;
        ob[3 * D4 + d4] = o;
    }
}

extern "C" void kernel_launch(void* const* d_in, const int* in_sizes, int n_in,
                              void* d_out, int out_size) {
    const float* x      = (const float*)d_in[0];  // [8,2048,4,1024]
    const float* h_res  = (const float*)d_in[1];  // [8,2048,4,4]
    const float* h_out  = (const float*)d_in[2];  // [8,2048,1024]
    const float* h_post = (const float*)d_in[3];  // [8,2048,4]
    float* out = (float*)d_out;                   // [8,2048,4,1024]

    stream_mix_kernel<<<TOKENS, 256>>>(x, h_res, h_out, h_post, out);
}